// round 8
// baseline (speedup 1.0000x reference)
#include <cuda_runtime.h>
#include <math.h>

#define BB   64
#define SS   2048
#define DD   1024
#define HH   300
#define OO   2
#define SCH  16                 // s-chunks for the big reduction
#define SPC  (SS / SCH)         // 128 s per chunk
#define D4   (DD / 4)           // 256 float4 per row

// Scratch (allocation-free rule: __device__ globals)
__device__ int   g_end[BB];
__device__ float g_euph[BB][DD];     // accumulated (unnormalized) segment sum

// ---------------------------------------------------------------------------
// 1) setup: end-index scan + zero g_euph + init out with b2.
//    end = first s with ids[b][s]==1, fallback B (reference's except-path).
// ---------------------------------------------------------------------------
__global__ __launch_bounds__(1024) void k_end(const int* __restrict__ ids,
                                              const float* __restrict__ b2,
                                              float* __restrict__ out) {
    int b = blockIdx.x;
    int t = threadIdx.x;
    __shared__ int m;
    if (t == 0) m = 0x7fffffff;

    g_euph[b][t] = 0.0f;                   // 1024 threads x 1024 d
    if (t < OO) out[b * OO + t] = b2[t];   // out accumulator starts at bias

    __syncthreads();
    const int2* row = (const int2*)(ids + b * SS);
    int2 v = row[t];                       // 1024 threads * 2 ids = 2048
    if (v.x == 1) atomicMin(&m, 2 * t);
    if (v.y == 1) atomicMin(&m, 2 * t + 1);
    __syncthreads();
    if (t == 0) g_end[b] = (m == 0x7fffffff) ? BB : m;
}

// ---------------------------------------------------------------------------
// 2) big masked segment-sum with COMPACTED row list (R5 win, ~at DRAM cap).
//    Chunk partials now land directly in g_euph via REDG float adds
//    (16 adds per element, spread addresses — noise), killing k_combine.
// ---------------------------------------------------------------------------
__global__ __launch_bounds__(256) void k_reduce(const float* __restrict__ x,
                                                const float* __restrict__ mask) {
    int b = blockIdx.x;
    int c = blockIdx.y;
    int t = threadIdx.x;
    int end = g_end[b];
    int s0  = c * SPC;

    __shared__ float s_m[SPC];
    __shared__ int   s_idx[SPC];
    __shared__ int   s_cnt;
    if (t == 0) s_cnt = 0;
    __syncthreads();

    if (t < SPC) {                          // first 128 threads stage+compact
        int s = s0 + t;
        float m = (s < end) ? mask[b * SS + s] : 0.0f;
        if (m != 0.0f) {
            int p = atomicAdd(&s_cnt, 1);
            s_idx[p] = t;
            s_m[p]   = m;
        }
    }
    __syncthreads();
    int n = s_cnt;

    const float4* xp = (const float4*)(x + (long long)b * SS * DD)
                       + (long long)s0 * D4 + t;

    float4 acc = make_float4(0.f, 0.f, 0.f, 0.f);
    int i = 0;
    for (; i + 4 <= n; i += 4) {
        int   j0 = s_idx[i],     j1 = s_idx[i + 1];
        int   j2 = s_idx[i + 2], j3 = s_idx[i + 3];
        float m0 = s_m[i],       m1 = s_m[i + 1];
        float m2 = s_m[i + 2],   m3 = s_m[i + 3];
        float4 v0 = xp[j0 * D4];
        float4 v1 = xp[j1 * D4];
        float4 v2 = xp[j2 * D4];
        float4 v3 = xp[j3 * D4];
        acc.x += v0.x * m0; acc.y += v0.y * m0; acc.z += v0.z * m0; acc.w += v0.w * m0;
        acc.x += v1.x * m1; acc.y += v1.y * m1; acc.z += v1.z * m1; acc.w += v1.w * m1;
        acc.x += v2.x * m2; acc.y += v2.y * m2; acc.z += v2.z * m2; acc.w += v2.w * m2;
        acc.x += v3.x * m3; acc.y += v3.y * m3; acc.z += v3.z * m3; acc.w += v3.w * m3;
    }
    for (; i < n; i++) {
        int   j = s_idx[i];
        float m = s_m[i];
        float4 v = xp[j * D4];
        acc.x += v.x * m; acc.y += v.y * m; acc.z += v.z * m; acc.w += v.w * m;
    }

    float* ep = g_euph[b] + 4 * t;
    atomicAdd(ep + 0, acc.x);
    atomicAdd(ep + 1, acc.y);
    atomicAdd(ep + 2, acc.z);
    atomicAdd(ep + 3, acc.w);
}

// ---------------------------------------------------------------------------
// 3) fused hidden+out: warp owns h, W1 row in regs, 4 batches per warp
//    (grid (16,75)=1200 blocks — the measured sweet spot). hidden[b][h] is
//    consumed immediately: lane 0 adds tanh(dot/end + b1) * W2[o][h] into
//    out[b][o] via REDG (out pre-seeded with b2 in k_end). Kills k_out.
// ---------------------------------------------------------------------------
__global__ __launch_bounds__(128) void k_hidden(const float* __restrict__ W1,
                                                const float* __restrict__ b1,
                                                const float* __restrict__ W2,
                                                float* __restrict__ out) {
    int warp = threadIdx.x >> 5;
    int lane = threadIdx.x & 31;
    int h    = blockIdx.y * 4 + warp;          // 75*4 = 300, always valid
    int b0   = blockIdx.x * 4;                 // 16*4  = 64

    const float4* w4p = (const float4*)(W1 + (long long)h * DD);
    float4 w[8];
#pragma unroll
    for (int i = 0; i < 8; i++) w[i] = w4p[lane + 32 * i];
    float bias = b1[h];
    float w2a  = W2[h];                        // W2[0][h]
    float w2b  = W2[HH + h];                   // W2[1][h]

#pragma unroll
    for (int bi = 0; bi < 4; bi++) {
        int b = b0 + bi;
        const float4* e4 = (const float4*)g_euph[b];
        float s = 0.f;
#pragma unroll
        for (int i = 0; i < 8; i++) {
            float4 e = e4[lane + 32 * i];
            s += e.x * w[i].x + e.y * w[i].y + e.z * w[i].z + e.w * w[i].w;
        }
#pragma unroll
        for (int off = 16; off > 0; off >>= 1)
            s += __shfl_xor_sync(0xffffffffu, s, off);
        if (lane == 0) {
            float hv = tanhf(s / (float)g_end[b] + bias);
            atomicAdd(&out[b * OO + 0], hv * w2a);
            atomicAdd(&out[b * OO + 1], hv * w2b);
        }
    }
}

// ---------------------------------------------------------------------------
extern "C" void kernel_launch(void* const* d_in, const int* in_sizes, int n_in,
                              void* d_out, int out_size) {
    const float* x    = (const float*)d_in[0];       // [B,S,D] f32
    const int*   ids  = (const int*)d_in[1];         // [B,S]   i32 (JAX x64 off)
    const float* mask = (const float*)d_in[2];       // [B,S,1] f32
    const float* W1   = (const float*)d_in[3];       // [H,D]
    const float* b1   = (const float*)d_in[4];       // [H]
    const float* W2   = (const float*)d_in[5];       // [OUT,H]
    const float* b2   = (const float*)d_in[6];       // [OUT]
    float*       out  = (float*)d_out;               // [B,OUT]

    k_end   <<<BB, 1024>>>(ids, b2, out);
    k_reduce<<<dim3(BB, SCH), 256>>>(x, mask);
    k_hidden<<<dim3(16, HH / 4), 128>>>(W1, b1, W2, out);
}